// round 15
// baseline (speedup 1.0000x reference)
#include <cuda_runtime.h>
#include <cuda_fp16.h>
#include <math.h>
#include <stdint.h>

#define N_ROWS 32768
#define DIM    256
#define KCODES 1024
#define MARGIN 0.5f
#define CAP    20

// ---------------- device scratch ----------------
__device__ __half g_Bh[(size_t)KCODES * DIM];      // CB hi (0.5 MB)
__device__ float  g_c2[KCODES];
__device__ float  g_probs[KCODES];
__device__ float  g_scal[2];
__device__ int    g_done = 0;                      // completion counter (self-resetting)

// ---------------- PTX helpers (sm_100-safe, no 'a' features) ----------------
__device__ __forceinline__ uint32_t smem_u32(const void* p) {
    uint32_t a;
    asm("{ .reg .u64 t; cvta.to.shared.u64 t, %1; cvt.u32.u64 %0, t; }" : "=r"(a) : "l"(p));
    return a;
}
__device__ __forceinline__ void cp_async16(uint32_t dst, const void* src) {
    asm volatile("cp.async.cg.shared.global [%0], [%1], 16;" :: "r"(dst), "l"(src) : "memory");
}
__device__ __forceinline__ void cp_commit() {
    asm volatile("cp.async.commit_group;" ::: "memory");
}
template <int N>
__device__ __forceinline__ void cp_wait() {
    asm volatile("cp.async.wait_group %0;" :: "n"(N) : "memory");
}
__device__ __forceinline__ void ldsm4(uint32_t* r, uint32_t addr) {
    asm volatile("ldmatrix.sync.aligned.m8n8.x4.shared.b16 {%0,%1,%2,%3}, [%4];"
                 : "=r"(r[0]), "=r"(r[1]), "=r"(r[2]), "=r"(r[3]) : "r"(addr));
}
__device__ __forceinline__ void mma_f16(float* d, const uint32_t* a, uint32_t b0, uint32_t b1) {
    asm volatile(
        "mma.sync.aligned.m16n8k16.row.col.f32.f16.f16.f32 "
        "{%0,%1,%2,%3}, {%4,%5,%6,%7}, {%8,%9}, {%0,%1,%2,%3};"
        : "+f"(d[0]), "+f"(d[1]), "+f"(d[2]), "+f"(d[3])
        : "r"(a[0]), "r"(a[1]), "r"(a[2]), "r"(a[3]), "r"(b0), "r"(b1));
}
// monotone float<->uint encoding for atomicMin on possibly-negative floats
__device__ __forceinline__ unsigned fenc(float f) {
    unsigned u = __float_as_uint(f);
    return (u & 0x80000000u) ? ~u : (u | 0x80000000u);
}
__device__ __forceinline__ float fdec(unsigned e) {
    unsigned u = (e & 0x80000000u) ? (e ^ 0x80000000u) : ~e;
    return __uint_as_float(u);     // NaN for init pattern; fminf handles it
}

// ---------------- setup: zero accumulators + fp16 codebook + norms ----------------
__global__ __launch_bounds__(256)
void vq_setup(const float* __restrict__ CB) {
    int gtid = blockIdx.x * blockDim.x + threadIdx.x;   // 32768 threads
    if (gtid < KCODES) g_probs[gtid] = 0.f;
    if (gtid < 2) g_scal[gtid] = 0.f;
    // fp16 conversion: 65536 float4 -> 2 per thread
    #pragma unroll
    for (int j = 0; j < 2; j++) {
        int i4 = gtid + j * 32768;
        float4 v = *(const float4*)(CB + (size_t)i4 * 4);
        half2 h0 = __floats2half2_rn(v.x, v.y);
        half2 h1 = __floats2half2_rn(v.z, v.w);
        uint2 u;
        u.x = *(const uint32_t*)&h0;
        u.y = *(const uint32_t*)&h1;
        *(uint2*)(g_Bh + (size_t)i4 * 4) = u;
    }
    // codebook norms: exactly 1024 warps, one per code, float4 loads
    int wid = gtid >> 5;
    int lane = gtid & 31;
    const float* c = CB + (size_t)wid * DIM + lane * 8;
    float4 a = *(const float4*)(c);
    float4 b = *(const float4*)(c + 4);
    float s = a.x*a.x + a.y*a.y + a.z*a.z + a.w*a.w
            + b.x*b.x + b.y*b.y + b.z*b.z + b.w*b.w;
    #pragma unroll
    for (int o = 16; o; o >>= 1) s += __shfl_down_sync(0xffffffffu, s, o);
    if (lane == 0) g_c2[wid] = s;
}

// ---------------- fused kernel (2 CTAs/SM, 8 warps/CTA, 32x64 warp tiles) ----------------
// Each CTA: 128 rows x all 1024 codes. 256 threads, 8 warps (4 row x 2 col), warp tile 32x64.
// A converted fp32->fp16 in-kernel into persistent smem. 8 bn chunks x 4 k-chunks = 32 steps,
// 2-stage B pipeline. Screening: per-row running min + candidate list (<=20/row), sync-free
// epilogue. Phase 2: warp-per-row exact fp32 refine + softmax + gather. Last CTA finalizes loss.
#define SH_A_B  528                    // bytes per A smem row (264 halves)
#define SH_B_B  144                    // bytes per B smem row (72 halves)
#define A_BYTES (128 * SH_A_B)         // 67584
#define B_STAGE_BYTES (128 * SH_B_B)   // 18432
#define OFF_B      67584
#define OFF_PROBS  104448
#define OFF_CAND   108544              // 128*20*2 = 5120
#define OFF_CNT    113664
#define OFF_RUNMIN 114176
#define OFF_DSCR   114688              // 8*20*4 = 640
#define FUSED_SMEM 115328

__global__ __launch_bounds__(256, 2)
void vq_fused(const float* __restrict__ X, const float* __restrict__ CB,
              float* __restrict__ out_q, float* __restrict__ out_loss,
              float* __restrict__ out_idx) {
    extern __shared__ __align__(16) char smem[];
    float*    s_probs  = (float*)(smem + OFF_PROBS);
    unsigned short* s_cand = (unsigned short*)(smem + OFF_CAND);  // [128][CAP]
    int*      s_cnt    = (int*)(smem + OFF_CNT);
    unsigned* s_runmin = (unsigned*)(smem + OFF_RUNMIN);
    float*    s_dscr   = (float*)(smem + OFF_DSCR);               // [8 warps][CAP]
    __shared__ int s_last;
    __shared__ float s_red[8];

    const int tid  = threadIdx.x;
    const int lane = tid & 31;
    const int wid  = tid >> 5;
    const int warp_row = wid & 3;     // 0..3
    const int warp_col = wid >> 2;    // 0..1
    const int bm = blockIdx.x;        // 0..255
    const uint32_t sbase = smem_u32(smem);

    // ---- init shared state ----
    for (int i = tid; i < KCODES; i += 256) s_probs[i] = 0.f;
    if (tid < 128) { s_runmin[tid] = 0xFFFFFFFFu; s_cnt[tid] = 0; }

    auto load_B = [&](int step) {
        const int bn = step >> 2, kc = step & 3, stage = step & 1;
        const uint32_t dB = sbase + OFF_B + stage * B_STAGE_BYTES;
        #pragma unroll
        for (int i = 0; i < 4; i++) {
            int idx = tid + i * 256;
            int row = idx >> 3, c16 = idx & 7;
            cp_async16(dB + row * SH_B_B + c16 * 16,
                       g_Bh + (size_t)(bn * 128 + row) * DIM + kc * 64 + c16 * 8);
        }
        cp_commit();
    };

    load_B(0);
    load_B(1);

    // ---- A conversion: X fp32 -> smem fp16 (overlaps B pipeline warmup) ----
    {
        const float* Xa = X + (size_t)(bm * 128) * DIM;
        #pragma unroll
        for (int i = 0; i < 32; i++) {
            int idx = tid + i * 256;          // 0..8191
            int row = idx >> 6;               // 0..127
            int c4i = idx & 63;               // float4 index in row
            float4 v = *(const float4*)(Xa + (size_t)row * DIM + c4i * 4);
            half2 h0 = __floats2half2_rn(v.x, v.y);
            half2 h1 = __floats2half2_rn(v.z, v.w);
            uint2 u;
            u.x = *(const uint32_t*)&h0;
            u.y = *(const uint32_t*)&h1;
            *(uint2*)(smem + row * SH_A_B + c4i * 8) = u;
        }
    }

    float acc[2][8][4];
    #pragma unroll
    for (int mt = 0; mt < 2; mt++)
        #pragma unroll
        for (int nn = 0; nn < 8; nn++)
            #pragma unroll
            for (int j = 0; j < 4; j++) acc[mt][nn][j] = 0.f;

    const int grp = lane >> 3;
    const int rin = lane & 7;
    const int r4 = lane >> 2;
    const int c4 = lane & 3;

    // ---- phase 1: 32 pipeline steps (8 bn chunks x 4 k-chunks) ----
    for (int step = 0; step < 32; step++) {
        if (step < 31) cp_wait<1>(); else cp_wait<0>();
        __syncthreads();

        const uint32_t bS = sbase + OFF_B + (step & 1) * B_STAGE_BYTES;
        const uint32_t kcA = (step & 3) * 128;

        #pragma unroll
        for (int ks = 0; ks < 4; ks++) {
            const uint32_t kbA = kcA + ks * 32;
            const uint32_t kbB = ks * 32;
            uint32_t a[2][4];
            #pragma unroll
            for (int mt = 0; mt < 2; mt++) {
                int arow = warp_row * 32 + mt * 16 + ((grp & 1) << 3) + rin;
                ldsm4(a[mt], sbase + arow * SH_A_B + kbA + (grp >> 1) * 16);
            }
            uint32_t b[8][2];
            #pragma unroll
            for (int np = 0; np < 4; np++) {
                int brow = warp_col * 64 + np * 16 + ((grp >> 1) << 3) + rin;
                uint32_t b4[4];
                ldsm4(b4, bS + brow * SH_B_B + kbB + (grp & 1) * 16);
                b[np * 2][0]     = b4[0]; b[np * 2][1]     = b4[1];
                b[np * 2 + 1][0] = b4[2]; b[np * 2 + 1][1] = b4[3];
            }
            #pragma unroll
            for (int nn = 0; nn < 8; nn++) {
                mma_f16(acc[0][nn], a[0], b[nn][0], b[nn][1]);
                mma_f16(acc[1][nn], a[1], b[nn][0], b[nn][1]);
            }
        }

        // barrier + prefetch BEFORE the epilogue so cp.async overlaps the FMA burst
        __syncthreads();
        if (step + 2 < 32) load_B(step + 2);

        if ((step & 3) == 3) {
            // ---- sync-free chunk epilogue ----
            const int bn = step >> 2;
            #pragma unroll
            for (int mt = 0; mt < 2; mt++) {
                const int r0 = warp_row * 32 + mt * 16 + r4;
                float mn0 = 3.4e38f, mn1 = 3.4e38f;
                #pragma unroll
                for (int nn = 0; nn < 8; nn++) {
                    int kb = bn * 128 + warp_col * 64 + nn * 8 + c4 * 2;
                    float c20 = g_c2[kb], c21 = g_c2[kb + 1];
                    mn0 = fminf(mn0, fminf(c20 - 2.f * acc[mt][nn][0], c21 - 2.f * acc[mt][nn][1]));
                    mn1 = fminf(mn1, fminf(c20 - 2.f * acc[mt][nn][2], c21 - 2.f * acc[mt][nn][3]));
                }
                mn0 = fminf(mn0, __shfl_xor_sync(0xffffffffu, mn0, 1));
                mn0 = fminf(mn0, __shfl_xor_sync(0xffffffffu, mn0, 2));
                mn1 = fminf(mn1, __shfl_xor_sync(0xffffffffu, mn1, 1));
                mn1 = fminf(mn1, __shfl_xor_sync(0xffffffffu, mn1, 2));
                float thr0 = fminf(fdec(s_runmin[r0]), mn0) + MARGIN;
                float thr1 = fminf(fdec(s_runmin[r0 + 8]), mn1) + MARGIN;
                #pragma unroll
                for (int nn = 0; nn < 8; nn++) {
                    int kb = bn * 128 + warp_col * 64 + nn * 8 + c4 * 2;
                    float c20 = g_c2[kb], c21 = g_c2[kb + 1];
                    float s00 = c20 - 2.f * acc[mt][nn][0];
                    float s01 = c21 - 2.f * acc[mt][nn][1];
                    float s10 = c20 - 2.f * acc[mt][nn][2];
                    float s11 = c21 - 2.f * acc[mt][nn][3];
                    if (s00 < thr0) { int p = atomicAdd(&s_cnt[r0], 1);     if (p < CAP) s_cand[r0 * CAP + p] = (unsigned short)kb; }
                    if (s01 < thr0) { int p = atomicAdd(&s_cnt[r0], 1);     if (p < CAP) s_cand[r0 * CAP + p] = (unsigned short)(kb + 1); }
                    if (s10 < thr1) { int p = atomicAdd(&s_cnt[r0 + 8], 1); if (p < CAP) s_cand[(r0 + 8) * CAP + p] = (unsigned short)kb; }
                    if (s11 < thr1) { int p = atomicAdd(&s_cnt[r0 + 8], 1); if (p < CAP) s_cand[(r0 + 8) * CAP + p] = (unsigned short)(kb + 1); }
                }
                if (c4 == 0) {
                    atomicMin(&s_runmin[r0], fenc(mn0));
                    atomicMin(&s_runmin[r0 + 8], fenc(mn1));
                }
                #pragma unroll
                for (int nn = 0; nn < 8; nn++)
                    #pragma unroll
                    for (int j = 0; j < 4; j++) acc[mt][nn][j] = 0.f;
            }
        }
    }

    // ---- phase 2: warp-per-row exact refine + softmax + gather ----
    __syncthreads();
    float ent_sum = 0.f, lat_acc = 0.f;

    for (int rr = 0; rr < 16; rr++) {
        const int lrow = wid * 16 + rr;
        const int n = bm * 128 + lrow;

        const float* xrow = X + (size_t)n * DIM + lane * 8;
        const float4 xr0 = *(const float4*)(xrow);
        const float4 xr1 = *(const float4*)(xrow + 4);

        int cntr = s_cnt[lrow];
        if (cntr > CAP) cntr = CAP;

        float dmin = 3.4e38f; int kmin = 0x7fffffff;
        for (int j = 0; j < cntr; j++) {
            int k = s_cand[lrow * CAP + j];
            const float* crow = CB + (size_t)k * DIM + lane * 8;
            float4 c0 = *(const float4*)(crow);
            float4 c1 = *(const float4*)(crow + 4);
            float f0 = xr0.x - c0.x, f1 = xr0.y - c0.y, f2 = xr0.z - c0.z, f3 = xr0.w - c0.w;
            float f4 = xr1.x - c1.x, f5 = xr1.y - c1.y, f6 = xr1.z - c1.z, f7 = xr1.w - c1.w;
            float d = f0*f0 + f1*f1 + f2*f2 + f3*f3 + f4*f4 + f5*f5 + f6*f6 + f7*f7;
            #pragma unroll
            for (int o = 16; o; o >>= 1) d += __shfl_xor_sync(0xffffffffu, d, o);
            if (lane == 0) s_dscr[wid * CAP + j] = d;
            if (d < dmin || (d == dmin && k < kmin)) { dmin = d; kmin = k; }
        }
        __syncwarp();

        if (lane == 0) {
            float Z = 0.f, S1 = 0.f;
            for (int j = 0; j < cntr; j++) {
                float dd = s_dscr[wid * CAP + j] - dmin;
                float e = expf(-100.f * dd);
                Z += e; S1 += e * dd;
            }
            float invZ = 1.f / Z;
            for (int j = 0; j < cntr; j++) {
                float dd = s_dscr[wid * CAP + j] - dmin;
                atomicAdd(&s_probs[s_cand[lrow * CAP + j]], expf(-100.f * dd) * invZ);
            }
            ent_sum += 100.f * (S1 * invZ) + logf(Z);
            lat_acc += dmin;
            if (out_idx) out_idx[n] = (float)kmin;
        }

        // gather quantized row
        const float* qrow = CB + (size_t)kmin * DIM + lane * 8;
        float4 q0 = *(const float4*)(qrow);
        float4 q1 = *(const float4*)(qrow + 4);
        *(float4*)(out_q + (size_t)n * DIM + lane * 8)     = q0;
        *(float4*)(out_q + (size_t)n * DIM + lane * 8 + 4) = q1;
    }

    __syncthreads();
    for (int i = tid; i < KCODES; i += 256) {
        float v = s_probs[i];
        if (v != 0.f) atomicAdd(&g_probs[i], v);
    }
    if (lane == 0) {
        atomicAdd(&g_scal[0], lat_acc);
        atomicAdd(&g_scal[1], ent_sum);
    }

    // ---- last-CTA finalize ----
    __threadfence();
    __syncthreads();
    if (tid == 0) s_last = (atomicAdd(&g_done, 1) == (int)gridDim.x - 1);
    __syncthreads();
    if (s_last) {
        __threadfence();
        float part = 0.f;
        #pragma unroll
        for (int j = 0; j < 4; j++) {
            float p = g_probs[tid + j * 256] * (1.0f / (float)N_ROWS);
            part += -p * logf(p + 1e-5f);
        }
        #pragma unroll
        for (int o = 16; o; o >>= 1) part += __shfl_down_sync(0xffffffffu, part, o);
        if (lane == 0) s_red[wid] = part;
        __syncthreads();
        if (wid == 0) {
            float v = (lane < 8) ? s_red[lane] : 0.f;
            #pragma unroll
            for (int o = 4; o; o >>= 1) v += __shfl_down_sync(0xffffffffu, v, o);
            if (lane == 0) {
                if (out_loss) {
                    float avg_entropy = v;
                    float sample_entropy = g_scal[1] * (1.0f / (float)N_ROWS);
                    float mean_lat = g_scal[0] * (1.0f / ((float)N_ROWS * (float)DIM));
                    float ent_loss = sample_entropy - avg_entropy;
                    *out_loss = 1.25f * mean_lat + 0.1f * ent_loss;
                }
                g_done = 0;    // self-reset for next graph replay
            }
        }
    }
}

// ---------------- launch ----------------
extern "C" void kernel_launch(void* const* d_in, const int* in_sizes, int n_in,
                              void* d_out, int out_size) {
    const float* X  = (const float*)d_in[0];
    const float* CB = (const float*)d_in[1];
    float* out = (float*)d_out;

    float* out_q    = out;
    float* out_loss = (out_size >= N_ROWS * DIM + 1) ? (out + (size_t)N_ROWS * DIM) : nullptr;
    float* out_idx  = (out_size >= N_ROWS * DIM + 1 + N_ROWS) ? (out + (size_t)N_ROWS * DIM + 1) : nullptr;

    static int smem_set = 0;
    if (!smem_set) {
        cudaFuncSetAttribute(vq_fused, cudaFuncAttributeMaxDynamicSharedMemorySize, FUSED_SMEM);
        smem_set = 1;
    }

    vq_setup<<<128, 256>>>(CB);
    vq_fused<<<N_ROWS / 128, 256, FUSED_SMEM>>>(X, CB, out_q, out_loss, out_idx);
}

// round 16
// speedup vs baseline: 1.0383x; 1.0383x over previous
#include <cuda_runtime.h>
#include <cuda_fp16.h>
#include <math.h>
#include <stdint.h>

#define N_ROWS 32768
#define DIM    256
#define KCODES 1024
#define MARGIN 0.5f
#define CAP    16

// ---------------- device scratch ----------------
__device__ __half g_Bh[(size_t)KCODES * DIM];      // CB hi (0.5 MB)
__device__ float  g_c2[KCODES];
__device__ float  g_probs[KCODES];
__device__ float  g_scal[2];
__device__ int    g_done = 0;                      // completion counter (self-resetting)

// ---------------- PTX helpers (sm_100-safe, no 'a' features) ----------------
__device__ __forceinline__ uint32_t smem_u32(const void* p) {
    uint32_t a;
    asm("{ .reg .u64 t; cvta.to.shared.u64 t, %1; cvt.u32.u64 %0, t; }" : "=r"(a) : "l"(p));
    return a;
}
__device__ __forceinline__ void cp_async16(uint32_t dst, const void* src) {
    asm volatile("cp.async.cg.shared.global [%0], [%1], 16;" :: "r"(dst), "l"(src) : "memory");
}
__device__ __forceinline__ void cp_commit() {
    asm volatile("cp.async.commit_group;" ::: "memory");
}
template <int N>
__device__ __forceinline__ void cp_wait() {
    asm volatile("cp.async.wait_group %0;" :: "n"(N) : "memory");
}
__device__ __forceinline__ void ldsm4(uint32_t* r, uint32_t addr) {
    asm volatile("ldmatrix.sync.aligned.m8n8.x4.shared.b16 {%0,%1,%2,%3}, [%4];"
                 : "=r"(r[0]), "=r"(r[1]), "=r"(r[2]), "=r"(r[3]) : "r"(addr));
}
__device__ __forceinline__ void mma_f16(float* d, const uint32_t* a, uint32_t b0, uint32_t b1) {
    asm volatile(
        "mma.sync.aligned.m16n8k16.row.col.f32.f16.f16.f32 "
        "{%0,%1,%2,%3}, {%4,%5,%6,%7}, {%8,%9}, {%0,%1,%2,%3};"
        : "+f"(d[0]), "+f"(d[1]), "+f"(d[2]), "+f"(d[3])
        : "r"(a[0]), "r"(a[1]), "r"(a[2]), "r"(a[3]), "r"(b0), "r"(b1));
}
// monotone float<->uint encoding for atomicMin on possibly-negative floats
__device__ __forceinline__ unsigned fenc(float f) {
    unsigned u = __float_as_uint(f);
    return (u & 0x80000000u) ? ~u : (u | 0x80000000u);
}
__device__ __forceinline__ float fdec(unsigned e) {
    unsigned u = (e & 0x80000000u) ? (e ^ 0x80000000u) : ~e;
    return __uint_as_float(u);     // NaN for init pattern; fminf handles it
}

// ---------------- setup: zero accumulators + fp16 codebook + norms ----------------
__global__ __launch_bounds__(256)
void vq_setup(const float* __restrict__ CB) {
    int gtid = blockIdx.x * blockDim.x + threadIdx.x;   // 32768 threads
    if (gtid < KCODES) g_probs[gtid] = 0.f;
    if (gtid < 2) g_scal[gtid] = 0.f;
    // fp16 conversion: 65536 float4 -> 2 per thread
    #pragma unroll
    for (int j = 0; j < 2; j++) {
        int i4 = gtid + j * 32768;
        float4 v = *(const float4*)(CB + (size_t)i4 * 4);
        half2 h0 = __floats2half2_rn(v.x, v.y);
        half2 h1 = __floats2half2_rn(v.z, v.w);
        uint2 u;
        u.x = *(const uint32_t*)&h0;
        u.y = *(const uint32_t*)&h1;
        *(uint2*)(g_Bh + (size_t)i4 * 4) = u;
    }
    // codebook norms: exactly 1024 warps, one per code, float4 loads
    int wid = gtid >> 5;
    int lane = gtid & 31;
    const float* c = CB + (size_t)wid * DIM + lane * 8;
    float4 a = *(const float4*)(c);
    float4 b = *(const float4*)(c + 4);
    float s = a.x*a.x + a.y*a.y + a.z*a.z + a.w*a.w
            + b.x*b.x + b.y*b.y + b.z*b.z + b.w*b.w;
    #pragma unroll
    for (int o = 16; o; o >>= 1) s += __shfl_down_sync(0xffffffffu, s, o);
    if (lane == 0) g_c2[wid] = s;
}

// ---------------- fused kernel (2 CTAs/SM, 8 warps/CTA, 32x64 warp tiles) ----------------
// Each CTA: 128 rows x all 1024 codes. 256 threads, 8 warps (4 row x 2 col), warp tile 32x64.
// A converted fp32->fp16 in-kernel into persistent smem. 8 bn chunks x 4 k-chunks = 32 steps,
// 2-stage B pipeline (load_B AFTER the chunk epilogue - R12 proven order). Screening: per-row
// running min + candidate list (<=16/row), sync-free epilogue. Phase 2: warp-per-row exact
// fp32 refine + softmax (prob atomics straight to global) + gather. Last CTA finalizes loss.
#define SH_A_B  528                    // bytes per A smem row (264 halves)
#define SH_B_B  144                    // bytes per B smem row (72 halves)
#define A_BYTES (128 * SH_A_B)         // 67584
#define B_STAGE_BYTES (128 * SH_B_B)   // 18432
#define OFF_B      67584
#define OFF_CAND   104448              // 128*16*2 = 4096
#define OFF_CNT    108544
#define OFF_RUNMIN 109056
#define OFF_DSCR   109568              // 8*16*4 = 512
#define FUSED_SMEM 110080

__global__ __launch_bounds__(256, 2)
void vq_fused(const float* __restrict__ X, const float* __restrict__ CB,
              float* __restrict__ out_q, float* __restrict__ out_loss,
              float* __restrict__ out_idx) {
    extern __shared__ __align__(16) char smem[];
    unsigned short* s_cand = (unsigned short*)(smem + OFF_CAND);  // [128][CAP]
    int*      s_cnt    = (int*)(smem + OFF_CNT);
    unsigned* s_runmin = (unsigned*)(smem + OFF_RUNMIN);
    float*    s_dscr   = (float*)(smem + OFF_DSCR);               // [8 warps][CAP]
    __shared__ int s_last;
    __shared__ float s_red[8];

    const int tid  = threadIdx.x;
    const int lane = tid & 31;
    const int wid  = tid >> 5;
    const int warp_row = wid & 3;     // 0..3
    const int warp_col = wid >> 2;    // 0..1
    const int bm = blockIdx.x;        // 0..255
    const uint32_t sbase = smem_u32(smem);

    // ---- init shared state ----
    if (tid < 128) { s_runmin[tid] = 0xFFFFFFFFu; s_cnt[tid] = 0; }

    auto load_B = [&](int step) {
        const int bn = step >> 2, kc = step & 3, stage = step & 1;
        const uint32_t dB = sbase + OFF_B + stage * B_STAGE_BYTES;
        #pragma unroll
        for (int i = 0; i < 4; i++) {
            int idx = tid + i * 256;
            int row = idx >> 3, c16 = idx & 7;
            cp_async16(dB + row * SH_B_B + c16 * 16,
                       g_Bh + (size_t)(bn * 128 + row) * DIM + kc * 64 + c16 * 8);
        }
        cp_commit();
    };

    load_B(0);
    load_B(1);

    // ---- A conversion: X fp32 -> smem fp16 (overlaps B pipeline warmup) ----
    {
        const float* Xa = X + (size_t)(bm * 128) * DIM;
        #pragma unroll
        for (int i = 0; i < 32; i++) {
            int idx = tid + i * 256;          // 0..8191
            int row = idx >> 6;               // 0..127
            int c4i = idx & 63;               // float4 index in row
            float4 v = *(const float4*)(Xa + (size_t)row * DIM + c4i * 4);
            half2 h0 = __floats2half2_rn(v.x, v.y);
            half2 h1 = __floats2half2_rn(v.z, v.w);
            uint2 u;
            u.x = *(const uint32_t*)&h0;
            u.y = *(const uint32_t*)&h1;
            *(uint2*)(smem + row * SH_A_B + c4i * 8) = u;
        }
    }

    float acc[2][8][4];
    #pragma unroll
    for (int mt = 0; mt < 2; mt++)
        #pragma unroll
        for (int nn = 0; nn < 8; nn++)
            #pragma unroll
            for (int j = 0; j < 4; j++) acc[mt][nn][j] = 0.f;

    const int grp = lane >> 3;
    const int rin = lane & 7;
    const int r4 = lane >> 2;
    const int c4 = lane & 3;

    // ---- phase 1: 32 pipeline steps (8 bn chunks x 4 k-chunks) ----
    for (int step = 0; step < 32; step++) {
        if (step < 31) cp_wait<1>(); else cp_wait<0>();
        __syncthreads();

        const uint32_t bS = sbase + OFF_B + (step & 1) * B_STAGE_BYTES;
        const uint32_t kcA = (step & 3) * 128;

        #pragma unroll
        for (int ks = 0; ks < 4; ks++) {
            const uint32_t kbA = kcA + ks * 32;
            const uint32_t kbB = ks * 32;
            uint32_t a[2][4];
            #pragma unroll
            for (int mt = 0; mt < 2; mt++) {
                int arow = warp_row * 32 + mt * 16 + ((grp & 1) << 3) + rin;
                ldsm4(a[mt], sbase + arow * SH_A_B + kbA + (grp >> 1) * 16);
            }
            uint32_t b[8][2];
            #pragma unroll
            for (int np = 0; np < 4; np++) {
                int brow = warp_col * 64 + np * 16 + ((grp >> 1) << 3) + rin;
                uint32_t b4[4];
                ldsm4(b4, bS + brow * SH_B_B + kbB + (grp & 1) * 16);
                b[np * 2][0]     = b4[0]; b[np * 2][1]     = b4[1];
                b[np * 2 + 1][0] = b4[2]; b[np * 2 + 1][1] = b4[3];
            }
            #pragma unroll
            for (int nn = 0; nn < 8; nn++) {
                mma_f16(acc[0][nn], a[0], b[nn][0], b[nn][1]);
                mma_f16(acc[1][nn], a[1], b[nn][0], b[nn][1]);
            }
        }

        if ((step & 3) == 3) {
            // ---- sync-free chunk epilogue ----
            const int bn = step >> 2;
            #pragma unroll
            for (int mt = 0; mt < 2; mt++) {
                const int r0 = warp_row * 32 + mt * 16 + r4;
                float mn0 = 3.4e38f, mn1 = 3.4e38f;
                #pragma unroll
                for (int nn = 0; nn < 8; nn++) {
                    int kb = bn * 128 + warp_col * 64 + nn * 8 + c4 * 2;
                    float c20 = g_c2[kb], c21 = g_c2[kb + 1];
                    mn0 = fminf(mn0, fminf(c20 - 2.f * acc[mt][nn][0], c21 - 2.f * acc[mt][nn][1]));
                    mn1 = fminf(mn1, fminf(c20 - 2.f * acc[mt][nn][2], c21 - 2.f * acc[mt][nn][3]));
                }
                mn0 = fminf(mn0, __shfl_xor_sync(0xffffffffu, mn0, 1));
                mn0 = fminf(mn0, __shfl_xor_sync(0xffffffffu, mn0, 2));
                mn1 = fminf(mn1, __shfl_xor_sync(0xffffffffu, mn1, 1));
                mn1 = fminf(mn1, __shfl_xor_sync(0xffffffffu, mn1, 2));
                float thr0 = fminf(fdec(s_runmin[r0]), mn0) + MARGIN;
                float thr1 = fminf(fdec(s_runmin[r0 + 8]), mn1) + MARGIN;
                #pragma unroll
                for (int nn = 0; nn < 8; nn++) {
                    int kb = bn * 128 + warp_col * 64 + nn * 8 + c4 * 2;
                    float c20 = g_c2[kb], c21 = g_c2[kb + 1];
                    float s00 = c20 - 2.f * acc[mt][nn][0];
                    float s01 = c21 - 2.f * acc[mt][nn][1];
                    float s10 = c20 - 2.f * acc[mt][nn][2];
                    float s11 = c21 - 2.f * acc[mt][nn][3];
                    if (s00 < thr0) { int p = atomicAdd(&s_cnt[r0], 1);     if (p < CAP) s_cand[r0 * CAP + p] = (unsigned short)kb; }
                    if (s01 < thr0) { int p = atomicAdd(&s_cnt[r0], 1);     if (p < CAP) s_cand[r0 * CAP + p] = (unsigned short)(kb + 1); }
                    if (s10 < thr1) { int p = atomicAdd(&s_cnt[r0 + 8], 1); if (p < CAP) s_cand[(r0 + 8) * CAP + p] = (unsigned short)kb; }
                    if (s11 < thr1) { int p = atomicAdd(&s_cnt[r0 + 8], 1); if (p < CAP) s_cand[(r0 + 8) * CAP + p] = (unsigned short)(kb + 1); }
                }
                if (c4 == 0) {
                    atomicMin(&s_runmin[r0], fenc(mn0));
                    atomicMin(&s_runmin[r0 + 8], fenc(mn1));
                }
                #pragma unroll
                for (int nn = 0; nn < 8; nn++)
                    #pragma unroll
                    for (int j = 0; j < 4; j++) acc[mt][nn][j] = 0.f;
            }
        }

        __syncthreads();
        if (step + 2 < 32) load_B(step + 2);
    }

    // ---- phase 2: warp-per-row exact refine + softmax + gather ----
    __syncthreads();
    float ent_sum = 0.f, lat_acc = 0.f;

    for (int rr = 0; rr < 16; rr++) {
        const int lrow = wid * 16 + rr;
        const int n = bm * 128 + lrow;

        const float* xrow = X + (size_t)n * DIM + lane * 8;
        const float4 xr0 = *(const float4*)(xrow);
        const float4 xr1 = *(const float4*)(xrow + 4);

        int cntr = s_cnt[lrow];
        if (cntr > CAP) cntr = CAP;

        float dmin = 3.4e38f; int kmin = 0x7fffffff;
        for (int j = 0; j < cntr; j++) {
            int k = s_cand[lrow * CAP + j];
            const float* crow = CB + (size_t)k * DIM + lane * 8;
            float4 c0 = *(const float4*)(crow);
            float4 c1 = *(const float4*)(crow + 4);
            float f0 = xr0.x - c0.x, f1 = xr0.y - c0.y, f2 = xr0.z - c0.z, f3 = xr0.w - c0.w;
            float f4 = xr1.x - c1.x, f5 = xr1.y - c1.y, f6 = xr1.z - c1.z, f7 = xr1.w - c1.w;
            float d = f0*f0 + f1*f1 + f2*f2 + f3*f3 + f4*f4 + f5*f5 + f6*f6 + f7*f7;
            #pragma unroll
            for (int o = 16; o; o >>= 1) d += __shfl_xor_sync(0xffffffffu, d, o);
            if (lane == 0) s_dscr[wid * CAP + j] = d;
            if (d < dmin || (d == dmin && k < kmin)) { dmin = d; kmin = k; }
        }
        __syncwarp();

        if (lane == 0) {
            float Z = 0.f, S1 = 0.f;
            for (int j = 0; j < cntr; j++) {
                float dd = s_dscr[wid * CAP + j] - dmin;
                float e = expf(-100.f * dd);
                Z += e; S1 += e * dd;
            }
            float invZ = 1.f / Z;
            for (int j = 0; j < cntr; j++) {
                float dd = s_dscr[wid * CAP + j] - dmin;
                atomicAdd(&g_probs[s_cand[lrow * CAP + j]], expf(-100.f * dd) * invZ);
            }
            ent_sum += 100.f * (S1 * invZ) + logf(Z);
            lat_acc += dmin;
            if (out_idx) out_idx[n] = (float)kmin;
        }

        // gather quantized row
        const float* qrow = CB + (size_t)kmin * DIM + lane * 8;
        float4 q0 = *(const float4*)(qrow);
        float4 q1 = *(const float4*)(qrow + 4);
        *(float4*)(out_q + (size_t)n * DIM + lane * 8)     = q0;
        *(float4*)(out_q + (size_t)n * DIM + lane * 8 + 4) = q1;
    }

    if (lane == 0) {
        atomicAdd(&g_scal[0], lat_acc);
        atomicAdd(&g_scal[1], ent_sum);
    }

    // ---- last-CTA finalize ----
    __threadfence();
    __syncthreads();
    if (tid == 0) s_last = (atomicAdd(&g_done, 1) == (int)gridDim.x - 1);
    __syncthreads();
    if (s_last) {
        __threadfence();
        float part = 0.f;
        #pragma unroll
        for (int j = 0; j < 4; j++) {
            float p = g_probs[tid + j * 256] * (1.0f / (float)N_ROWS);
            part += -p * logf(p + 1e-5f);
        }
        #pragma unroll
        for (int o = 16; o; o >>= 1) part += __shfl_down_sync(0xffffffffu, part, o);
        if (lane == 0) s_red[wid] = part;
        __syncthreads();
        if (wid == 0) {
            float v = (lane < 8) ? s_red[lane] : 0.f;
            #pragma unroll
            for (int o = 4; o; o >>= 1) v += __shfl_down_sync(0xffffffffu, v, o);
            if (lane == 0) {
                if (out_loss) {
                    float avg_entropy = v;
                    float sample_entropy = g_scal[1] * (1.0f / (float)N_ROWS);
                    float mean_lat = g_scal[0] * (1.0f / ((float)N_ROWS * (float)DIM));
                    float ent_loss = sample_entropy - avg_entropy;
                    *out_loss = 1.25f * mean_lat + 0.1f * ent_loss;
                }
                g_done = 0;    // self-reset for next graph replay
            }
        }
    }
}

// ---------------- launch ----------------
extern "C" void kernel_launch(void* const* d_in, const int* in_sizes, int n_in,
                              void* d_out, int out_size) {
    const float* X  = (const float*)d_in[0];
    const float* CB = (const float*)d_in[1];
    float* out = (float*)d_out;

    float* out_q    = out;
    float* out_loss = (out_size >= N_ROWS * DIM + 1) ? (out + (size_t)N_ROWS * DIM) : nullptr;
    float* out_idx  = (out_size >= N_ROWS * DIM + 1 + N_ROWS) ? (out + (size_t)N_ROWS * DIM + 1) : nullptr;

    static int smem_set = 0;
    if (!smem_set) {
        cudaFuncSetAttribute(vq_fused, cudaFuncAttributeMaxDynamicSharedMemorySize, FUSED_SMEM);
        smem_set = 1;
    }

    vq_setup<<<128, 256>>>(CB);
    vq_fused<<<N_ROWS / 128, 256, FUSED_SMEM>>>(X, CB, out_q, out_loss, out_idx);
}